// round 9
// baseline (speedup 1.0000x reference)
#include <cuda_runtime.h>
#include <math.h>

#define BB 1024
#define CC 64
#define DD 256
#define NN 512
#define K2 (2*DD)
#define DELTA 1e-4f

// global scratch: pre-split tf32 (hi,lo) planes
__device__ float2 g_A2[BB * K2];            // stacked [b][k]: x_in | x_ctx (unscaled)
__device__ float2 g_B2[(size_t)CC * K2 * NN]; // stacked [c][k][n]: Wff | 0.3*Wctx
__device__ float  g_boost[CC * NN];

// ---- tf32 split ----
__device__ __forceinline__ float2 split1(float f) {
    unsigned h;
    asm("cvt.rna.tf32.f32 %0, %1;" : "=r"(h) : "f"(f));
    float hf = __uint_as_float(h);
    return make_float2(hf, f - hf);
}
__device__ __forceinline__ void mma_tf32(
    float& c0, float& c1, float& c2, float& c3,
    unsigned a0, unsigned a1, unsigned a2, unsigned a3,
    unsigned b0, unsigned b1)
{
    asm("mma.sync.aligned.m16n8k8.row.col.f32.tf32.tf32.f32 "
        "{%0,%1,%2,%3},{%4,%5,%6,%7},{%8,%9},{%0,%1,%2,%3};"
        : "+f"(c0), "+f"(c1), "+f"(c2), "+f"(c3)
        : "r"(a0), "r"(a1), "r"(a2), "r"(a3), "r"(b0), "r"(b1));
}

// ---------------------------------------------------------------------------
// prep kernels
// ---------------------------------------------------------------------------
__global__ void boost_kernel(const float* __restrict__ avg) {
    int i = blockIdx.x * blockDim.x + threadIdx.x;
    if (i < CC * NN) g_boost[i] = log1pf(0.05f / (avg[i] + 1e-6f));
}

__global__ void prep_A(const float* __restrict__ x_in, const float* __restrict__ x_ctx) {
    int i = blockIdx.x * blockDim.x + threadIdx.x;
    if (i < BB * K2) {
        int b = i >> 9, k = i & (K2 - 1);
        float v = (k < DD) ? x_in[(b << 8) + k] : x_ctx[(b << 8) + k - DD];
        g_A2[i] = split1(v);
    }
}

__global__ void prep_B(const float* __restrict__ Wff, const float* __restrict__ Wctx) {
    size_t i = (size_t)blockIdx.x * blockDim.x + threadIdx.x;   // < CC*K2*NN/4
    size_t flat = i * 4;
    int n = (int)(flat % NN);
    size_t kc = flat / NN;
    int k = (int)(kc % K2);
    int c = (int)(kc / K2);
    float4 v;
    if (k < DD) {
        v = *reinterpret_cast<const float4*>(Wff + ((size_t)c * DD + k) * NN + n);
    } else {
        v = *reinterpret_cast<const float4*>(Wctx + ((size_t)c * DD + (k - DD)) * NN + n);
        v.x *= 0.3f; v.y *= 0.3f; v.z *= 0.3f; v.w *= 0.3f;
    }
    float2 s0 = split1(v.x), s1 = split1(v.y), s2 = split1(v.z), s3 = split1(v.w);
    float4* dst = reinterpret_cast<float4*>(g_B2 + flat);
    dst[0] = make_float4(s0.x, s0.y, s1.x, s1.y);
    dst[1] = make_float4(s2.x, s2.y, s3.x, s3.y);
}

// ---------------------------------------------------------------------------
// Kernel 1: drive GEMM, 3xTF32, pre-split operands, pure LDS.64+MMA mainloop.
// Block 128x128, BK=16, double-buffered dynamic smem.
// A smem: [m][k] float2, k-stride 20  (STS.128 stores, conflict-free LDS.64)
// B smem: [k][n] float2, n-stride 132 (STS.128 stores, conflict-free LDS.64)
// ---------------------------------------------------------------------------
#define A_STRIDE 20
#define B_STRIDE 132
#define A_BUF (128 * A_STRIDE)
#define B_BUF (16 * B_STRIDE)
#define DRIVE_SMEM ((2 * A_BUF + 2 * B_BUF) * (int)sizeof(float2))

__global__ __launch_bounds__(256, 2) void drive_gemm(
    const float* __restrict__ bias, float* __restrict__ act)
{
    extern __shared__ float2 smem2[];
    float2* As2 = smem2;                 // [2][128][A_STRIDE]
    float2* Bs2 = smem2 + 2 * A_BUF;     // [2][16][B_STRIDE]

    int c  = blockIdx.z;
    int m0 = blockIdx.y * 128;
    int n0 = blockIdx.x * 128;
    int tid  = threadIdx.x;
    int warp = tid >> 5, lane = tid & 31;
    int wm = (warp & 1) * 64;
    int wn = (warp >> 1) * 32;
    int ar = lane >> 2;
    int ac = lane & 3;

    // loader coords
    int am  = tid >> 1, akh = (tid & 1) * 8;   // A: row am, k-offset akh (float2 units)
    int bk  = tid >> 4, bn  = (tid & 15) * 8;  // B: k-row bk, n-offset bn

    float acc[16][4];
    #pragma unroll
    for (int i = 0; i < 16; i++)
        #pragma unroll
        for (int j = 0; j < 4; j++) acc[i][j] = 0.f;

    const float2* gA = g_A2 + (size_t)(m0 + am) * K2 + akh;
    const float2* gB = g_B2 + ((size_t)c * K2 + bk) * NN + n0 + bn;

    // ---- preload k-tile 0 ----
    {
        const float4* pA = reinterpret_cast<const float4*>(gA);
        float4* sA = reinterpret_cast<float4*>(&As2[am * A_STRIDE + akh]);
        #pragma unroll
        for (int i = 0; i < 4; i++) sA[i] = pA[i];
        const float4* pB = reinterpret_cast<const float4*>(gB);
        float4* sB = reinterpret_cast<float4*>(&Bs2[bk * B_STRIDE + bn]);
        #pragma unroll
        for (int i = 0; i < 4; i++) sB[i] = pB[i];
    }
    __syncthreads();

    int cur = 0;
    for (int kt = 0; kt < K2 / 16; kt++) {
        float4 pa[4], pb[4];
        bool has_next = (kt + 1 < K2 / 16);
        if (has_next) {
            int k0 = (kt + 1) * 16;
            const float4* pA = reinterpret_cast<const float4*>(gA + k0);
            #pragma unroll
            for (int i = 0; i < 4; i++) pa[i] = pA[i];
            const float4* pB = reinterpret_cast<const float4*>(gB + (size_t)k0 * NN);
            #pragma unroll
            for (int i = 0; i < 4; i++) pb[i] = pB[i];
        }

        const float2* Ab = As2 + cur * A_BUF;
        const float2* Bb = Bs2 + cur * B_BUF;

        #pragma unroll
        for (int kh = 0; kh < 2; kh++) {
            int kk0 = kh * 8;
            unsigned bh[8], bl[8];
            #pragma unroll
            for (int sn = 0; sn < 4; sn++) {
                float2 b0 = Bb[(kk0 + ac    ) * B_STRIDE + wn + sn * 8 + ar];
                float2 b1 = Bb[(kk0 + ac + 4) * B_STRIDE + wn + sn * 8 + ar];
                bh[sn*2+0] = __float_as_uint(b0.x); bl[sn*2+0] = __float_as_uint(b0.y);
                bh[sn*2+1] = __float_as_uint(b1.x); bl[sn*2+1] = __float_as_uint(b1.y);
            }
            #pragma unroll
            for (int sm = 0; sm < 4; sm++) {
                int mb = wm + sm * 16;
                float2 A0 = Ab[(mb + ar    ) * A_STRIDE + kk0 + ac];
                float2 A1 = Ab[(mb + ar + 8) * A_STRIDE + kk0 + ac];
                float2 A2 = Ab[(mb + ar    ) * A_STRIDE + kk0 + ac + 4];
                float2 A3 = Ab[(mb + ar + 8) * A_STRIDE + kk0 + ac + 4];
                unsigned ah0 = __float_as_uint(A0.x), al0 = __float_as_uint(A0.y);
                unsigned ah1 = __float_as_uint(A1.x), al1 = __float_as_uint(A1.y);
                unsigned ah2 = __float_as_uint(A2.x), al2 = __float_as_uint(A2.y);
                unsigned ah3 = __float_as_uint(A3.x), al3 = __float_as_uint(A3.y);
                #pragma unroll
                for (int sn = 0; sn < 4; sn++) {
                    float* cp = acc[sm * 4 + sn];
                    mma_tf32(cp[0], cp[1], cp[2], cp[3],
                             ah0, ah1, ah2, ah3, bh[sn*2], bh[sn*2+1]);
                    mma_tf32(cp[0], cp[1], cp[2], cp[3],
                             ah0, ah1, ah2, ah3, bl[sn*2], bl[sn*2+1]);
                    mma_tf32(cp[0], cp[1], cp[2], cp[3],
                             al0, al1, al2, al3, bh[sn*2], bh[sn*2+1]);
                }
            }
        }

        if (has_next) {
            int nxt = cur ^ 1;
            float4* sA = reinterpret_cast<float4*>(&As2[nxt * A_BUF + am * A_STRIDE + akh]);
            #pragma unroll
            for (int i = 0; i < 4; i++) sA[i] = pa[i];
            float4* sB = reinterpret_cast<float4*>(&Bs2[nxt * B_BUF + bk * B_STRIDE + bn]);
            #pragma unroll
            for (int i = 0; i < 4; i++) sB[i] = pb[i];
            __syncthreads();
            cur = nxt;
        }
    }

    // ---- epilogue: + bias, scatter ----
    const float* bc = bias + (size_t)c * NN;
    #pragma unroll
    for (int sm = 0; sm < 4; sm++) {
        #pragma unroll
        for (int sn = 0; sn < 4; sn++) {
            const float* cp = acc[sm * 4 + sn];
            int col = n0 + wn + sn * 8 + ac * 2;
            float bx = bc[col], by = bc[col + 1];
            int r0 = m0 + wm + sm * 16 + ar;
            float2 v0 = make_float2(cp[0] + bx, cp[1] + by);
            float2 v1 = make_float2(cp[2] + bx, cp[3] + by);
            *reinterpret_cast<float2*>(act + ((size_t)r0 * CC + c) * NN + col)       = v0;
            *reinterpret_cast<float2*>(act + ((size_t)(r0 + 8) * CC + c) * NN + col) = v1;
        }
    }
}

// ---------------------------------------------------------------------------
// Kernel 2: warp-per-row k-WTA with margin-exact selection + normalize +
//           sparse pred/err.  (round-7 design, unchanged)
// ---------------------------------------------------------------------------
__device__ __forceinline__ unsigned f2ord(float f) {
    unsigned u = __float_as_uint(f);
    return (u & 0x80000000u) ? ~u : (u | 0x80000000u);
}
__device__ __forceinline__ float ord2f(unsigned u) {
    unsigned v = (u & 0x80000000u) ? (u & 0x7FFFFFFFu) : ~u;
    return __uint_as_float(v);
}

__global__ __launch_bounds__(256) void topk_pred(
    const int* __restrict__ kptr, const float* __restrict__ x_in,
    const float* __restrict__ x_ctx,
    const float* __restrict__ Wff, const float* __restrict__ Wctx,
    const float* __restrict__ bias,
    const float* __restrict__ Wp,
    float* __restrict__ act, float* __restrict__ pred, float* __restrict__ err)
{
    int lane = threadIdx.x & 31;
    int w    = threadIdx.x >> 5;
    int row  = blockIdx.x * 8 + w;          // b*C + c
    int c = row & (CC - 1);
    int b = row >> 6;

    __shared__ float s_vv[8][64];
    __shared__ int   s_ii[8][64];
    __shared__ int   s_bi[8][32];
    __shared__ float s_be[8][32];
    __shared__ int   s_bf[8][32];

    const float4* arow = reinterpret_cast<const float4*>(act + (size_t)row * NN);
    const float4* brow = reinterpret_cast<const float4*>(g_boost + (size_t)c * NN);

    float    f[16];
    float    bf[16];
    unsigned u[16];
    #pragma unroll
    for (int i = 0; i < 4; i++) {
        float4 a  = arow[i * 32 + lane];
        float4 bo = brow[i * 32 + lane];
        f[i*4+0] = a.x; f[i*4+1] = a.y; f[i*4+2] = a.z; f[i*4+3] = a.w;
        bf[i*4+0] = a.x + bo.x; bf[i*4+1] = a.y + bo.y;
        bf[i*4+2] = a.z + bo.z; bf[i*4+3] = a.w + bo.w;
        #pragma unroll
        for (int q = 0; q < 4; q++) u[i*4+q] = f2ord(bf[i*4+q]);
    }

    int k = *kptr;

    unsigned lmax = 0;
    #pragma unroll
    for (int s = 0; s < 16; s++) lmax = max(lmax, u[s]);
    unsigned mx = lmax, lb = lmax;
    #pragma unroll
    for (int o = 16; o; o >>= 1) {
        mx = max(mx, __shfl_xor_sync(0xffffffffu, mx, o));
        lb = min(lb, __shfl_xor_sync(0xffffffffu, lb, o));
    }
    if (k > 32) lb = 0u;

    unsigned diff = mx ^ lb;
    unsigned T;
    int topbit;
    if (diff == 0u) { T = mx; topbit = -1; }
    else {
        topbit = 31 - __clz(diff);
        unsigned mask = (topbit == 31) ? 0xFFFFFFFFu : ((2u << topbit) - 1u);
        T = mx & ~mask;
    }
    for (int bit = topbit; bit >= 0; --bit) {
        unsigned cand = T | (1u << bit);
        int cnt = 0;
        #pragma unroll
        for (int s = 0; s < 16; s++) cnt += (u[s] >= cand) ? 1 : 0;
        #pragma unroll
        for (int o = 16; o; o >>= 1) cnt += __shfl_xor_sync(0xffffffffu, cnt, o);
        if (cnt >= k) T = cand;
    }
    float Tf = ord2f(T);
    float thi = Tf + DELTA, tlo = Tf - DELTA;

    int nhi = 0, nbo = 0;
    #pragma unroll
    for (int s = 0; s < 16; s++) {
        nhi += (bf[s] > thi) ? 1 : 0;
        nbo += (bf[s] >= tlo && bf[s] <= thi) ? 1 : 0;
    }
    #pragma unroll
    for (int o = 16; o; o >>= 1) {
        nhi += __shfl_xor_sync(0xffffffffu, nhi, o);
        nbo += __shfl_xor_sync(0xffffffffu, nbo, o);
    }
    int r = k - nhi;

    bool win[16];
    if (nbo == r || nbo > 32) {
        #pragma unroll
        for (int s = 0; s < 16; s++) win[s] = (bf[s] >= tlo);
        if (nbo > 32) {
            #pragma unroll
            for (int s = 0; s < 16; s++) win[s] = (u[s] >= T);
        }
    } else {
        int bpos[16];
        int base = 0;
        #pragma unroll
        for (int i = 0; i < 4; i++) {
            #pragma unroll
            for (int q = 0; q < 4; q++) {
                int s = i * 4 + q;
                bool isb = (bf[s] >= tlo && bf[s] <= thi);
                unsigned m = __ballot_sync(0xffffffffu, isb);
                bpos[s] = -1;
                if (isb) {
                    int pos = base + __popc(m & ((1u << lane) - 1u));
                    bpos[s] = pos;
                    s_bi[w][pos] = i * 128 + lane * 4 + q;
                }
                base += __popc(m);
            }
        }
        __syncwarp();
        int mcnt = base;
        const float* xi = x_in  + (size_t)b * DD;
        const float* xc = x_ctx + (size_t)b * DD;
        for (int e = 0; e < mcnt; e++) {
            int ncol = s_bi[w][e];
            const float* wf = Wff  + ((size_t)c * DD) * NN + ncol;
            const float* wc = Wctx + ((size_t)c * DD) * NN + ncol;
            float aff = 0.f, act2 = 0.f;
            #pragma unroll
            for (int t = 0; t < 8; t++) {
                int d = lane + t * 32;
                aff  = fmaf(xi[d], wf[(size_t)d * NN], aff);
                act2 = fmaf(xc[d], wc[(size_t)d * NN], act2);
            }
            #pragma unroll
            for (int o = 16; o; o >>= 1) {
                aff  += __shfl_xor_sync(0xffffffffu, aff,  o);
                act2 += __shfl_xor_sync(0xffffffffu, act2, o);
            }
            if (lane == 0)
                s_be[w][e] = aff + act2 * 0.3f + bias[(size_t)c * NN + ncol]
                           + g_boost[(size_t)c * NN + ncol];
            __syncwarp();
        }
        if (lane < mcnt) {
            float v = s_be[w][lane];
            int g = 0;
            for (int j = 0; j < mcnt; j++) g += (s_be[w][j] > v) ? 1 : 0;
            s_bf[w][lane] = (g < r) ? 1 : 0;
        }
        __syncwarp();
        #pragma unroll
        for (int s = 0; s < 16; s++) {
            bool isb = (bpos[s] >= 0);
            win[s] = (bf[s] > thi) || (isb && s_bf[w][bpos[s]]);
        }
    }

    float lsum = 0.f;
    #pragma unroll
    for (int s = 0; s < 16; s++) {
        float rl = fmaxf(f[s], 0.f);
        lsum += win[s] ? rl : 0.f;
    }
    #pragma unroll
    for (int o = 16; o; o >>= 1) lsum += __shfl_xor_sync(0xffffffffu, lsum, o);
    float scale = (float)k / (lsum + 1e-8f);

    float4* orow = reinterpret_cast<float4*>(act + (size_t)row * NN);
    int cnt_total = 0;
    #pragma unroll
    for (int i = 0; i < 4; i++) {
        float ov[4];
        #pragma unroll
        for (int q = 0; q < 4; q++) {
            int s = i * 4 + q;
            float rl  = fmaxf(f[s], 0.f);
            float val = win[s] ? rl * scale : 0.f;
            ov[q] = val;
            bool put = win[s] && (rl > 0.f);
            unsigned m = __ballot_sync(0xffffffffu, put);
            if (put) {
                int pos = cnt_total + __popc(m & ((1u << lane) - 1u));
                if (pos < 64) {
                    s_ii[w][pos] = i * 128 + lane * 4 + q;
                    s_vv[w][pos] = val;
                }
            }
            cnt_total += __popc(m);
        }
        orow[i * 32 + lane] = make_float4(ov[0], ov[1], ov[2], ov[3]);
    }
    if (cnt_total > 64) cnt_total = 64;
    __syncwarp();

    const float* WpC = Wp + (size_t)c * NN * DD;
    float4 acc0 = make_float4(0.f, 0.f, 0.f, 0.f);
    float4 acc1 = make_float4(0.f, 0.f, 0.f, 0.f);
    for (int j = 0; j < cnt_total; j++) {
        float vj = s_vv[w][j];
        const float4* wr = reinterpret_cast<const float4*>(WpC + (size_t)s_ii[w][j] * DD);
        float4 w0 = wr[lane];
        float4 w1 = wr[lane + 32];
        acc0.x = fmaf(vj, w0.x, acc0.x); acc0.y = fmaf(vj, w0.y, acc0.y);
        acc0.z = fmaf(vj, w0.z, acc0.z); acc0.w = fmaf(vj, w0.w, acc0.w);
        acc1.x = fmaf(vj, w1.x, acc1.x); acc1.y = fmaf(vj, w1.y, acc1.y);
        acc1.z = fmaf(vj, w1.z, acc1.z); acc1.w = fmaf(vj, w1.w, acc1.w);
    }

    const float4* xr = reinterpret_cast<const float4*>(x_in + (size_t)b * DD);
    float4 x0 = xr[lane], x1 = xr[lane + 32];
    float4* prow = reinterpret_cast<float4*>(pred + (size_t)row * DD);
    float4* erow = reinterpret_cast<float4*>(err  + (size_t)row * DD);
    prow[lane]      = acc0;
    prow[lane + 32] = acc1;
    erow[lane]      = make_float4(x0.x - acc0.x, x0.y - acc0.y, x0.z - acc0.z, x0.w - acc0.w);
    erow[lane + 32] = make_float4(x1.x - acc1.x, x1.y - acc1.y, x1.z - acc1.z, x1.w - acc1.w);
}

// ---------------------------------------------------------------------------
extern "C" void kernel_launch(void* const* d_in, const int* in_sizes, int n_in,
                              void* d_out, int out_size)
{
    const float* x_in  = (const float*)d_in[0];
    const float* x_ctx = (const float*)d_in[1];
    const float* Wff   = (const float*)d_in[2];
    const float* Wctx  = (const float*)d_in[3];
    const float* Wpred = (const float*)d_in[4];
    const float* bias  = (const float*)d_in[5];
    const float* avg   = (const float*)d_in[6];
    const int*   kptr  = (const int*)d_in[7];

    float* act  = (float*)d_out;                              // [B,C,N]
    float* pred = act  + (size_t)BB * CC * NN;                // [B,C,D]
    float* err  = pred + (size_t)BB * CC * DD;                // [B,C,D]

    // opt-in to >48KB dynamic smem (idempotent; not a stream op)
    cudaFuncSetAttribute(drive_gemm,
                         cudaFuncAttributeMaxDynamicSharedMemorySize, DRIVE_SMEM);

    boost_kernel<<<(CC * NN + 255) / 256, 256>>>(avg);
    prep_A<<<(BB * K2 + 255) / 256, 256>>>(x_in, x_ctx);
    prep_B<<<(int)(((size_t)CC * K2 * NN / 4 + 255) / 256), 256>>>(Wff, Wctx);

    dim3 g1(NN / 128, BB / 128, CC);
    drive_gemm<<<g1, 256, DRIVE_SMEM>>>(bias, act);

    topk_pred<<<BB * CC / 8, 256>>>(kptr, x_in, x_ctx, Wff, Wctx, bias,
                                    Wpred, act, pred, err);
}

// round 10
// speedup vs baseline: 1.3440x; 1.3440x over previous
#include <cuda_runtime.h>
#include <math.h>

#define BB 1024
#define CC 64
#define DD 256
#define NN 512
#define K2 (2*DD)
#define DELTA 1e-4f

// pre-split A plane: [b][k] stacked x_in | 0.3*x_ctx as (hi,lo)
__device__ float2 g_A2[BB * K2];
__device__ float  g_boost[CC * NN];

// ---- tf32 split ----
__device__ __forceinline__ float2 split1(float f) {
    unsigned h;
    asm("cvt.rna.tf32.f32 %0, %1;" : "=r"(h) : "f"(f));
    float hf = __uint_as_float(h);
    return make_float2(hf, f - hf);
}
__device__ __forceinline__ void mma_tf32(
    float& c0, float& c1, float& c2, float& c3,
    unsigned a0, unsigned a1, unsigned a2, unsigned a3,
    unsigned b0, unsigned b1)
{
    asm("mma.sync.aligned.m16n8k8.row.col.f32.tf32.tf32.f32 "
        "{%0,%1,%2,%3},{%4,%5,%6,%7},{%8,%9},{%0,%1,%2,%3};"
        : "+f"(c0), "+f"(c1), "+f"(c2), "+f"(c3)
        : "r"(a0), "r"(a1), "r"(a2), "r"(a3), "r"(b0), "r"(b1));
}

// ---------------------------------------------------------------------------
// prep kernels
// ---------------------------------------------------------------------------
__global__ void boost_kernel(const float* __restrict__ avg) {
    int i = blockIdx.x * blockDim.x + threadIdx.x;
    if (i < CC * NN) g_boost[i] = log1pf(0.05f / (avg[i] + 1e-6f));
}

__global__ void prep_A(const float* __restrict__ x_in, const float* __restrict__ x_ctx) {
    int i = blockIdx.x * blockDim.x + threadIdx.x;
    if (i < BB * K2) {
        int b = i >> 9, k = i & (K2 - 1);
        float v = (k < DD) ? x_in[(b << 8) + k] : 0.3f * x_ctx[(b << 8) + k - DD];
        g_A2[i] = split1(v);
    }
}

// ---------------------------------------------------------------------------
// Kernel 1: drive GEMM, 3xTF32. A pre-split (float2 smem, [m][k] stride 20),
// B raw fp32 (round-7 per-fragment split). 128x128x16, double-buffered.
// ---------------------------------------------------------------------------
#define A_ST   20                 // float2 stride per m-row
#define A_BUFSZ (128 * A_ST)      // float2 per buffer (20 KB)
#define B_LD   136                // float stride per k-row
#define B_BUFSZ (16 * B_LD)       // floats per buffer (8.7 KB)
#define DRIVE_SMEM (2 * A_BUFSZ * (int)sizeof(float2) + 2 * B_BUFSZ * (int)sizeof(float))

__global__ __launch_bounds__(256, 2) void drive_gemm(
    const float* __restrict__ Wff, const float* __restrict__ Wctx,
    const float* __restrict__ bias, float* __restrict__ act)
{
    extern __shared__ char sm_raw[];
    float2* As2 = reinterpret_cast<float2*>(sm_raw);                       // [2][128][A_ST]
    float*  Bs  = reinterpret_cast<float*>(sm_raw + 2 * A_BUFSZ * sizeof(float2)); // [2][16][B_LD]

    int c  = blockIdx.z;
    int m0 = blockIdx.y * 128;
    int n0 = blockIdx.x * 128;
    int tid  = threadIdx.x;
    int warp = tid >> 5, lane = tid & 31;
    int wm = (warp & 1) * 64;
    int wn = (warp >> 1) * 32;
    int ar = lane >> 2;
    int ac = lane & 3;

    // loader coords
    int am  = tid >> 1, akq = (tid & 1) * 8;        // A: row am, 8 float2 from akq

    float acc[16][4];
    #pragma unroll
    for (int i = 0; i < 16; i++)
        #pragma unroll
        for (int j = 0; j < 4; j++) acc[i][j] = 0.f;

    const float* WffC  = Wff  + (size_t)c * DD * NN;
    const float* WctxC = Wctx + (size_t)c * DD * NN;
    const float2* gA   = g_A2 + (size_t)(m0 + am) * K2 + akq;

    // ---- preload k-tile 0 ----
    {
        const float4* pA = reinterpret_cast<const float4*>(gA);
        float4* sA = reinterpret_cast<float4*>(&As2[am * A_ST + akq]);
        #pragma unroll
        for (int i = 0; i < 4; i++) sA[i] = pA[i];
        #pragma unroll
        for (int i = 0; i < 2; i++) {
            int t = tid + i * 256;
            int kk = t >> 5, nq = (t & 31) << 2;
            *reinterpret_cast<float4*>(&Bs[kk * B_LD + nq]) =
                *reinterpret_cast<const float4*>(WffC + (size_t)kk * NN + n0 + nq);
        }
    }
    __syncthreads();

    int cur = 0;
    for (int kt = 0; kt < K2 / 16; kt++) {
        float4 pa[4], pb[2];
        bool has_next = (kt + 1 < K2 / 16);
        if (has_next) {
            int k0 = (kt + 1) * 16;
            const float4* pA = reinterpret_cast<const float4*>(gA + k0);
            #pragma unroll
            for (int i = 0; i < 4; i++) pa[i] = pA[i];
            const float* wsrc = (k0 < DD) ? (WffC + (size_t)k0 * NN)
                                          : (WctxC + (size_t)(k0 - DD) * NN);
            #pragma unroll
            for (int i = 0; i < 2; i++) {
                int t = tid + i * 256;
                int kk = t >> 5, nq = (t & 31) << 2;
                pb[i] = *reinterpret_cast<const float4*>(wsrc + (size_t)kk * NN + n0 + nq);
            }
        }

        const float2* Ab = As2 + cur * A_BUFSZ;
        const float*  Bb = Bs  + cur * B_BUFSZ;

        #pragma unroll
        for (int kh = 0; kh < 2; kh++) {
            int kk0 = kh * 8;
            // B fragments: split per use (round-7 numerics)
            unsigned bh[8], bl[8];
            #pragma unroll
            for (int sn = 0; sn < 4; sn++) {
                float b0 = Bb[(kk0 + ac    ) * B_LD + wn + sn * 8 + ar];
                float b1 = Bb[(kk0 + ac + 4) * B_LD + wn + sn * 8 + ar];
                float2 s0 = split1(b0), s1 = split1(b1);
                bh[sn*2+0] = __float_as_uint(s0.x); bl[sn*2+0] = __float_as_uint(s0.y);
                bh[sn*2+1] = __float_as_uint(s1.x); bl[sn*2+1] = __float_as_uint(s1.y);
            }
            #pragma unroll
            for (int sm = 0; sm < 4; sm++) {
                int mb = wm + sm * 16;
                float2 A0 = Ab[(mb + ar    ) * A_ST + kk0 + ac];
                float2 A1 = Ab[(mb + ar + 8) * A_ST + kk0 + ac];
                float2 A2 = Ab[(mb + ar    ) * A_ST + kk0 + ac + 4];
                float2 A3 = Ab[(mb + ar + 8) * A_ST + kk0 + ac + 4];
                unsigned ah0 = __float_as_uint(A0.x), al0 = __float_as_uint(A0.y);
                unsigned ah1 = __float_as_uint(A1.x), al1 = __float_as_uint(A1.y);
                unsigned ah2 = __float_as_uint(A2.x), al2 = __float_as_uint(A2.y);
                unsigned ah3 = __float_as_uint(A3.x), al3 = __float_as_uint(A3.y);
                #pragma unroll
                for (int sn = 0; sn < 4; sn++) {
                    float* cp = acc[sm * 4 + sn];
                    mma_tf32(cp[0], cp[1], cp[2], cp[3],
                             ah0, ah1, ah2, ah3, bh[sn*2], bh[sn*2+1]);
                    mma_tf32(cp[0], cp[1], cp[2], cp[3],
                             ah0, ah1, ah2, ah3, bl[sn*2], bl[sn*2+1]);
                    mma_tf32(cp[0], cp[1], cp[2], cp[3],
                             al0, al1, al2, al3, bh[sn*2], bh[sn*2+1]);
                }
            }
        }

        if (has_next) {
            int nxt = cur ^ 1;
            float4* sA = reinterpret_cast<float4*>(&As2[nxt * A_BUFSZ + am * A_ST + akq]);
            #pragma unroll
            for (int i = 0; i < 4; i++) sA[i] = pa[i];
            #pragma unroll
            for (int i = 0; i < 2; i++) {
                int t = tid + i * 256;
                int kk = t >> 5, nq = (t & 31) << 2;
                *reinterpret_cast<float4*>(&Bs[nxt * B_BUFSZ + kk * B_LD + nq]) = pb[i];
            }
            __syncthreads();
            cur = nxt;
        }
    }

    // ---- epilogue: + bias, scatter ----
    const float* bc = bias + (size_t)c * NN;
    #pragma unroll
    for (int sm = 0; sm < 4; sm++) {
        #pragma unroll
        for (int sn = 0; sn < 4; sn++) {
            const float* cp = acc[sm * 4 + sn];
            int col = n0 + wn + sn * 8 + ac * 2;
            float bx = bc[col], by = bc[col + 1];
            int r0 = m0 + wm + sm * 16 + ar;
            float2 v0 = make_float2(cp[0] + bx, cp[1] + by);
            float2 v1 = make_float2(cp[2] + bx, cp[3] + by);
            *reinterpret_cast<float2*>(act + ((size_t)r0 * CC + c) * NN + col)       = v0;
            *reinterpret_cast<float2*>(act + ((size_t)(r0 + 8) * CC + c) * NN + col) = v1;
        }
    }
}

// ---------------------------------------------------------------------------
// Kernel 2: warp-per-row k-WTA with margin-exact selection + normalize +
//           sparse pred/err.  (round-7 design, unchanged)
// ---------------------------------------------------------------------------
__device__ __forceinline__ unsigned f2ord(float f) {
    unsigned u = __float_as_uint(f);
    return (u & 0x80000000u) ? ~u : (u | 0x80000000u);
}
__device__ __forceinline__ float ord2f(unsigned u) {
    unsigned v = (u & 0x80000000u) ? (u & 0x7FFFFFFFu) : ~u;
    return __uint_as_float(v);
}

__global__ __launch_bounds__(256) void topk_pred(
    const int* __restrict__ kptr, const float* __restrict__ x_in,
    const float* __restrict__ x_ctx,
    const float* __restrict__ Wff, const float* __restrict__ Wctx,
    const float* __restrict__ bias,
    const float* __restrict__ Wp,
    float* __restrict__ act, float* __restrict__ pred, float* __restrict__ err)
{
    int lane = threadIdx.x & 31;
    int w    = threadIdx.x >> 5;
    int row  = blockIdx.x * 8 + w;          // b*C + c
    int c = row & (CC - 1);
    int b = row >> 6;

    __shared__ float s_vv[8][64];
    __shared__ int   s_ii[8][64];
    __shared__ int   s_bi[8][32];
    __shared__ float s_be[8][32];
    __shared__ int   s_bf[8][32];

    const float4* arow = reinterpret_cast<const float4*>(act + (size_t)row * NN);
    const float4* brow = reinterpret_cast<const float4*>(g_boost + (size_t)c * NN);

    float    f[16];
    float    bf[16];
    unsigned u[16];
    #pragma unroll
    for (int i = 0; i < 4; i++) {
        float4 a  = arow[i * 32 + lane];
        float4 bo = brow[i * 32 + lane];
        f[i*4+0] = a.x; f[i*4+1] = a.y; f[i*4+2] = a.z; f[i*4+3] = a.w;
        bf[i*4+0] = a.x + bo.x; bf[i*4+1] = a.y + bo.y;
        bf[i*4+2] = a.z + bo.z; bf[i*4+3] = a.w + bo.w;
        #pragma unroll
        for (int q = 0; q < 4; q++) u[i*4+q] = f2ord(bf[i*4+q]);
    }

    int k = *kptr;

    unsigned lmax = 0;
    #pragma unroll
    for (int s = 0; s < 16; s++) lmax = max(lmax, u[s]);
    unsigned mx = lmax, lb = lmax;
    #pragma unroll
    for (int o = 16; o; o >>= 1) {
        mx = max(mx, __shfl_xor_sync(0xffffffffu, mx, o));
        lb = min(lb, __shfl_xor_sync(0xffffffffu, lb, o));
    }
    if (k > 32) lb = 0u;

    unsigned diff = mx ^ lb;
    unsigned T;
    int topbit;
    if (diff == 0u) { T = mx; topbit = -1; }
    else {
        topbit = 31 - __clz(diff);
        unsigned mask = (topbit == 31) ? 0xFFFFFFFFu : ((2u << topbit) - 1u);
        T = mx & ~mask;
    }
    for (int bit = topbit; bit >= 0; --bit) {
        unsigned cand = T | (1u << bit);
        int cnt = 0;
        #pragma unroll
        for (int s = 0; s < 16; s++) cnt += (u[s] >= cand) ? 1 : 0;
        #pragma unroll
        for (int o = 16; o; o >>= 1) cnt += __shfl_xor_sync(0xffffffffu, cnt, o);
        if (cnt >= k) T = cand;
    }
    float Tf = ord2f(T);
    float thi = Tf + DELTA, tlo = Tf - DELTA;

    int nhi = 0, nbo = 0;
    #pragma unroll
    for (int s = 0; s < 16; s++) {
        nhi += (bf[s] > thi) ? 1 : 0;
        nbo += (bf[s] >= tlo && bf[s] <= thi) ? 1 : 0;
    }
    #pragma unroll
    for (int o = 16; o; o >>= 1) {
        nhi += __shfl_xor_sync(0xffffffffu, nhi, o);
        nbo += __shfl_xor_sync(0xffffffffu, nbo, o);
    }
    int r = k - nhi;

    bool win[16];
    if (nbo == r || nbo > 32) {
        #pragma unroll
        for (int s = 0; s < 16; s++) win[s] = (bf[s] >= tlo);
        if (nbo > 32) {
            #pragma unroll
            for (int s = 0; s < 16; s++) win[s] = (u[s] >= T);
        }
    } else {
        int bpos[16];
        int base = 0;
        #pragma unroll
        for (int i = 0; i < 4; i++) {
            #pragma unroll
            for (int q = 0; q < 4; q++) {
                int s = i * 4 + q;
                bool isb = (bf[s] >= tlo && bf[s] <= thi);
                unsigned m = __ballot_sync(0xffffffffu, isb);
                bpos[s] = -1;
                if (isb) {
                    int pos = base + __popc(m & ((1u << lane) - 1u));
                    bpos[s] = pos;
                    s_bi[w][pos] = i * 128 + lane * 4 + q;
                }
                base += __popc(m);
            }
        }
        __syncwarp();
        int mcnt = base;
        const float* xi = x_in  + (size_t)b * DD;
        const float* xc = x_ctx + (size_t)b * DD;
        for (int e = 0; e < mcnt; e++) {
            int ncol = s_bi[w][e];
            const float* wf = Wff  + ((size_t)c * DD) * NN + ncol;
            const float* wc = Wctx + ((size_t)c * DD) * NN + ncol;
            float aff = 0.f, act2 = 0.f;
            #pragma unroll
            for (int t = 0; t < 8; t++) {
                int d = lane + t * 32;
                aff  = fmaf(xi[d], wf[(size_t)d * NN], aff);
                act2 = fmaf(xc[d], wc[(size_t)d * NN], act2);
            }
            #pragma unroll
            for (int o = 16; o; o >>= 1) {
                aff  += __shfl_xor_sync(0xffffffffu, aff,  o);
                act2 += __shfl_xor_sync(0xffffffffu, act2, o);
            }
            if (lane == 0)
                s_be[w][e] = aff + act2 * 0.3f + bias[(size_t)c * NN + ncol]
                           + g_boost[(size_t)c * NN + ncol];
            __syncwarp();
        }
        if (lane < mcnt) {
            float v = s_be[w][lane];
            int g = 0;
            for (int j = 0; j < mcnt; j++) g += (s_be[w][j] > v) ? 1 : 0;
            s_bf[w][lane] = (g < r) ? 1 : 0;
        }
        __syncwarp();
        #pragma unroll
        for (int s = 0; s < 16; s++) {
            bool isb = (bpos[s] >= 0);
            win[s] = (bf[s] > thi) || (isb && s_bf[w][bpos[s]]);
        }
    }

    float lsum = 0.f;
    #pragma unroll
    for (int s = 0; s < 16; s++) {
        float rl = fmaxf(f[s], 0.f);
        lsum += win[s] ? rl : 0.f;
    }
    #pragma unroll
    for (int o = 16; o; o >>= 1) lsum += __shfl_xor_sync(0xffffffffu, lsum, o);
    float scale = (float)k / (lsum + 1e-8f);

    float4* orow = reinterpret_cast<float4*>(act + (size_t)row * NN);
    int cnt_total = 0;
    #pragma unroll
    for (int i = 0; i < 4; i++) {
        float ov[4];
        #pragma unroll
        for (int q = 0; q < 4; q++) {
            int s = i * 4 + q;
            float rl  = fmaxf(f[s], 0.f);
            float val = win[s] ? rl * scale : 0.f;
            ov[q] = val;
            bool put = win[s] && (rl > 0.f);
            unsigned m = __ballot_sync(0xffffffffu, put);
            if (put) {
                int pos = cnt_total + __popc(m & ((1u << lane) - 1u));
                if (pos < 64) {
                    s_ii[w][pos] = i * 128 + lane * 4 + q;
                    s_vv[w][pos] = val;
                }
            }
            cnt_total += __popc(m);
        }
        orow[i * 32 + lane] = make_float4(ov[0], ov[1], ov[2], ov[3]);
    }
    if (cnt_total > 64) cnt_total = 64;
    __syncwarp();

    const float* WpC = Wp + (size_t)c * NN * DD;
    float4 acc0 = make_float4(0.f, 0.f, 0.f, 0.f);
    float4 acc1 = make_float4(0.f, 0.f, 0.f, 0.f);
    for (int j = 0; j < cnt_total; j++) {
        float vj = s_vv[w][j];
        const float4* wr = reinterpret_cast<const float4*>(WpC + (size_t)s_ii[w][j] * DD);
        float4 w0 = wr[lane];
        float4 w1 = wr[lane + 32];
        acc0.x = fmaf(vj, w0.x, acc0.x); acc0.y = fmaf(vj, w0.y, acc0.y);
        acc0.z = fmaf(vj, w0.z, acc0.z); acc0.w = fmaf(vj, w0.w, acc0.w);
        acc1.x = fmaf(vj, w1.x, acc1.x); acc1.y = fmaf(vj, w1.y, acc1.y);
        acc1.z = fmaf(vj, w1.z, acc1.z); acc1.w = fmaf(vj, w1.w, acc1.w);
    }

    const float4* xr = reinterpret_cast<const float4*>(x_in + (size_t)b * DD);
    float4 x0 = xr[lane], x1 = xr[lane + 32];
    float4* prow = reinterpret_cast<float4*>(pred + (size_t)row * DD);
    float4* erow = reinterpret_cast<float4*>(err  + (size_t)row * DD);
    prow[lane]      = acc0;
    prow[lane + 32] = acc1;
    erow[lane]      = make_float4(x0.x - acc0.x, x0.y - acc0.y, x0.z - acc0.z, x0.w - acc0.w);
    erow[lane + 32] = make_float4(x1.x - acc1.x, x1.y - acc1.y, x1.z - acc1.z, x1.w - acc1.w);
}

// ---------------------------------------------------------------------------
extern "C" void kernel_launch(void* const* d_in, const int* in_sizes, int n_in,
                              void* d_out, int out_size)
{
    const float* x_in  = (const float*)d_in[0];
    const float* x_ctx = (const float*)d_in[1];
    const float* Wff   = (const float*)d_in[2];
    const float* Wctx  = (const float*)d_in[3];
    const float* Wpred = (const float*)d_in[4];
    const float* bias  = (const float*)d_in[5];
    const float* avg   = (const float*)d_in[6];
    const int*   kptr  = (const int*)d_in[7];

    float* act  = (float*)d_out;                              // [B,C,N]
    float* pred = act  + (size_t)BB * CC * NN;                // [B,C,D]
    float* err  = pred + (size_t)BB * CC * DD;                // [B,C,D]

    cudaFuncSetAttribute(drive_gemm,
                         cudaFuncAttributeMaxDynamicSharedMemorySize, DRIVE_SMEM);

    boost_kernel<<<(CC * NN + 255) / 256, 256>>>(avg);
    prep_A<<<(BB * K2 + 255) / 256, 256>>>(x_in, x_ctx);

    dim3 g1(NN / 128, BB / 128, CC);
    drive_gemm<<<g1, 256, DRIVE_SMEM>>>(Wff, Wctx, bias, act);

    topk_pred<<<BB * CC / 8, 256>>>(kptr, x_in, x_ctx, Wff, Wctx, bias,
                                    Wpred, act, pred, err);
}

// round 11
// speedup vs baseline: 1.8087x; 1.3457x over previous
#include <cuda_runtime.h>
#include <math.h>

#define BB 1024
#define CC 64
#define DD 256
#define NN 512
#define K2 (2*DD)
#define DELTA 1e-4f

__device__ float g_boost[CC*NN];

// ---------------------------------------------------------------------------
// Kernel 0: boost[c,n] = log1p(0.05/(avg+1e-6))   (batch-independent)
// ---------------------------------------------------------------------------
__global__ void boost_kernel(const float* __restrict__ avg) {
    int i = blockIdx.x * blockDim.x + threadIdx.x;
    if (i < CC * NN) g_boost[i] = log1pf(0.05f / (avg[i] + 1e-6f));
}

// ---- tf32 split ----
__device__ __forceinline__ float2 split1(float f) {
    unsigned h;
    asm("cvt.rna.tf32.f32 %0, %1;" : "=r"(h) : "f"(f));
    float hf = __uint_as_float(h);
    return make_float2(hf, f - hf);
}
__device__ __forceinline__ void mma_tf32(
    float& c0, float& c1, float& c2, float& c3,
    unsigned a0, unsigned a1, unsigned a2, unsigned a3,
    unsigned b0, unsigned b1)
{
    asm("mma.sync.aligned.m16n8k8.row.col.f32.tf32.tf32.f32 "
        "{%0,%1,%2,%3},{%4,%5,%6,%7},{%8,%9},{%0,%1,%2,%3};"
        : "+f"(c0), "+f"(c1), "+f"(c2), "+f"(c3)
        : "r"(a0), "r"(a1), "r"(a2), "r"(a3), "r"(b0), "r"(b1));
}

// ---------------------------------------------------------------------------
// Kernel 1: drive GEMM via 3xTF32 — EXACT round-7 kernel (measured best).
// ---------------------------------------------------------------------------
__global__ __launch_bounds__(256) void drive_gemm(
    const float* __restrict__ x_in, const float* __restrict__ x_ctx,
    const float* __restrict__ Wff,  const float* __restrict__ Wctx,
    const float* __restrict__ bias, float* __restrict__ act)
{
    const int BM = 128, BN = 128, BK = 16, LD = 136;
    __shared__ float As[2][BK][LD];
    __shared__ float Bs[2][BK][LD];

    int c  = blockIdx.z;
    int m0 = blockIdx.y * BM;
    int n0 = blockIdx.x * BN;
    int tid  = threadIdx.x;
    int warp = tid >> 5, lane = tid & 31;
    int wm = (warp & 1) * 64;
    int wn = (warp >> 1) * 32;
    int ar = lane >> 2;
    int ac = lane & 3;

    float acc[16][4];
    #pragma unroll
    for (int i = 0; i < 16; i++)
        #pragma unroll
        for (int j = 0; j < 4; j++) acc[i][j] = 0.f;

    const float* WffC  = Wff  + (size_t)c * DD * NN;
    const float* WctxC = Wctx + (size_t)c * DD * NN;

    {
        #pragma unroll
        for (int i = 0; i < 2; i++) {
            int t = tid + i * 256;
            int m = t >> 2, kq = (t & 3) << 2;
            float4 v = *reinterpret_cast<const float4*>(x_in + (size_t)(m0 + m) * DD + kq);
            As[0][kq+0][m] = v.x; As[0][kq+1][m] = v.y;
            As[0][kq+2][m] = v.z; As[0][kq+3][m] = v.w;
        }
        #pragma unroll
        for (int i = 0; i < 2; i++) {
            int t = tid + i * 256;
            int kk = t >> 5, nq = (t & 31) << 2;
            *reinterpret_cast<float4*>(&Bs[0][kk][nq]) =
                *reinterpret_cast<const float4*>(WffC + (size_t)kk * NN + n0 + nq);
        }
    }
    __syncthreads();

    int cur = 0;
    for (int kt = 0; kt < K2 / BK; kt++) {
        float4 pa[2], pb[2];
        float  nscale = 1.0f;
        bool   has_next = (kt + 1 < K2 / BK);
        if (has_next) {
            int k0 = (kt + 1) * BK;
            const float* asrc = (k0 < DD) ? (x_in + k0) : (x_ctx + (k0 - DD));
            nscale = (k0 < DD) ? 1.0f : 0.3f;
            #pragma unroll
            for (int i = 0; i < 2; i++) {
                int t = tid + i * 256;
                int m = t >> 2, kq = (t & 3) << 2;
                pa[i] = *reinterpret_cast<const float4*>(asrc + (size_t)(m0 + m) * DD + kq);
            }
            const float* wsrc = (k0 < DD) ? (WffC + (size_t)k0 * NN)
                                          : (WctxC + (size_t)(k0 - DD) * NN);
            #pragma unroll
            for (int i = 0; i < 2; i++) {
                int t = tid + i * 256;
                int kk = t >> 5, nq = (t & 31) << 2;
                pb[i] = *reinterpret_cast<const float4*>(wsrc + (size_t)kk * NN + n0 + nq);
            }
        }

        #pragma unroll
        for (int kh = 0; kh < 2; kh++) {
            int kk0 = kh * 8;
            unsigned bh[8], bl[8];
            #pragma unroll
            for (int sn = 0; sn < 4; sn++) {
                float b0 = Bs[cur][kk0 + ac    ][wn + sn * 8 + ar];
                float b1 = Bs[cur][kk0 + ac + 4][wn + sn * 8 + ar];
                float2 s0 = split1(b0), s1 = split1(b1);
                bh[sn*2+0] = __float_as_uint(s0.x); bl[sn*2+0] = __float_as_uint(s0.y);
                bh[sn*2+1] = __float_as_uint(s1.x); bl[sn*2+1] = __float_as_uint(s1.y);
            }
            #pragma unroll
            for (int sm = 0; sm < 4; sm++) {
                int mb = wm + sm * 16;
                float a0 = As[cur][kk0 + ac    ][mb + ar];
                float a1 = As[cur][kk0 + ac    ][mb + ar + 8];
                float a2 = As[cur][kk0 + ac + 4][mb + ar];
                float a3 = As[cur][kk0 + ac + 4][mb + ar + 8];
                float2 sa0 = split1(a0), sa1 = split1(a1);
                float2 sa2 = split1(a2), sa3 = split1(a3);
                unsigned ah0 = __float_as_uint(sa0.x), al0 = __float_as_uint(sa0.y);
                unsigned ah1 = __float_as_uint(sa1.x), al1 = __float_as_uint(sa1.y);
                unsigned ah2 = __float_as_uint(sa2.x), al2 = __float_as_uint(sa2.y);
                unsigned ah3 = __float_as_uint(sa3.x), al3 = __float_as_uint(sa3.y);
                #pragma unroll
                for (int sn = 0; sn < 4; sn++) {
                    float* cp = acc[sm * 4 + sn];
                    mma_tf32(cp[0], cp[1], cp[2], cp[3],
                             ah0, ah1, ah2, ah3, bh[sn*2], bh[sn*2+1]);
                    mma_tf32(cp[0], cp[1], cp[2], cp[3],
                             ah0, ah1, ah2, ah3, bl[sn*2], bl[sn*2+1]);
                    mma_tf32(cp[0], cp[1], cp[2], cp[3],
                             al0, al1, al2, al3, bh[sn*2], bh[sn*2+1]);
                }
            }
        }

        if (has_next) {
            int nxt = cur ^ 1;
            #pragma unroll
            for (int i = 0; i < 2; i++) {
                int t = tid + i * 256;
                int m = t >> 2, kq = (t & 3) << 2;
                As[nxt][kq+0][m] = pa[i].x * nscale;
                As[nxt][kq+1][m] = pa[i].y * nscale;
                As[nxt][kq+2][m] = pa[i].z * nscale;
                As[nxt][kq+3][m] = pa[i].w * nscale;
            }
            #pragma unroll
            for (int i = 0; i < 2; i++) {
                int t = tid + i * 256;
                int kk = t >> 5, nq = (t & 31) << 2;
                *reinterpret_cast<float4*>(&Bs[nxt][kk][nq]) = pb[i];
            }
            __syncthreads();
            cur = nxt;
        }
    }

    const float* bc = bias + (size_t)c * NN;
    #pragma unroll
    for (int sm = 0; sm < 4; sm++) {
        #pragma unroll
        for (int sn = 0; sn < 4; sn++) {
            const float* cp = acc[sm * 4 + sn];
            int col = n0 + wn + sn * 8 + ac * 2;
            float bx = bc[col], by = bc[col + 1];
            int r0 = m0 + wm + sm * 16 + ar;
            float2 v0 = make_float2(cp[0] + bx, cp[1] + by);
            float2 v1 = make_float2(cp[2] + bx, cp[3] + by);
            *reinterpret_cast<float2*>(act + ((size_t)r0 * CC + c) * NN + col)       = v0;
            *reinterpret_cast<float2*>(act + ((size_t)(r0 + 8) * CC + c) * NN + col) = v1;
        }
    }
}

// ---------------------------------------------------------------------------
// Kernel 2: warp-per-row k-WTA, margin-exact, register-dieted.
// All margin compares in ordered-uint space; rare path uses a shared bitmap.
// ---------------------------------------------------------------------------
__device__ __forceinline__ unsigned f2ord(float f) {
    unsigned u = __float_as_uint(f);
    return (u & 0x80000000u) ? ~u : (u | 0x80000000u);
}
__device__ __forceinline__ float ord2f(unsigned u) {
    unsigned v = (u & 0x80000000u) ? (u & 0x7FFFFFFFu) : ~u;
    return __uint_as_float(v);
}

__global__ __launch_bounds__(256, 4) void topk_pred(
    const int* __restrict__ kptr, const float* __restrict__ x_in,
    const float* __restrict__ x_ctx,
    const float* __restrict__ Wff, const float* __restrict__ Wctx,
    const float* __restrict__ bias,
    const float* __restrict__ Wp,
    float* __restrict__ act, float* __restrict__ pred, float* __restrict__ err)
{
    int lane = threadIdx.x & 31;
    int w    = threadIdx.x >> 5;
    int row  = blockIdx.x * 8 + w;          // b*C + c
    int c = row & (CC - 1);
    int b = row >> 6;

    __shared__ float s_vv[8][64];
    __shared__ int   s_ii[8][64];
    __shared__ int   s_bi[8][32];     // borderline column indices (rare path)
    __shared__ float s_be[8][32];     // borderline exact boosted values
    __shared__ unsigned s_bm[8][16];  // rare-path winner bitmap (512 bits)

    const float4* arow = reinterpret_cast<const float4*>(act + (size_t)row * NN);
    const float4* brow = reinterpret_cast<const float4*>(g_boost + (size_t)c * NN);

    float    f[16];
    unsigned u[16];
    #pragma unroll
    for (int i = 0; i < 4; i++) {
        float4 a  = arow[i * 32 + lane];
        float4 bo = brow[i * 32 + lane];
        f[i*4+0] = a.x; f[i*4+1] = a.y; f[i*4+2] = a.z; f[i*4+3] = a.w;
        u[i*4+0] = f2ord(a.x + bo.x);
        u[i*4+1] = f2ord(a.y + bo.y);
        u[i*4+2] = f2ord(a.z + bo.z);
        u[i*4+3] = f2ord(a.w + bo.w);
    }

    int k = *kptr;

    // ---- binary search for k-th largest ordered value ----
    unsigned lmax = 0;
    #pragma unroll
    for (int s = 0; s < 16; s++) lmax = max(lmax, u[s]);
    unsigned mx = lmax, lb = lmax;
    #pragma unroll
    for (int o = 16; o; o >>= 1) {
        mx = max(mx, __shfl_xor_sync(0xffffffffu, mx, o));
        lb = min(lb, __shfl_xor_sync(0xffffffffu, lb, o));
    }
    if (k > 32) lb = 0u;

    unsigned diff = mx ^ lb;
    unsigned T;
    int topbit;
    if (diff == 0u) { T = mx; topbit = -1; }
    else {
        topbit = 31 - __clz(diff);
        unsigned mask = (topbit == 31) ? 0xFFFFFFFFu : ((2u << topbit) - 1u);
        T = mx & ~mask;
    }
    for (int bit = topbit; bit >= 0; --bit) {
        unsigned cand = T | (1u << bit);
        int cnt = 0;
        #pragma unroll
        for (int s = 0; s < 16; s++) cnt += (u[s] >= cand) ? 1 : 0;
        #pragma unroll
        for (int o = 16; o; o >>= 1) cnt += __shfl_xor_sync(0xffffffffu, cnt, o);
        if (cnt >= k) T = cand;
    }
    float Tf = ord2f(T);
    unsigned Uhi = f2ord(Tf + DELTA);
    unsigned Ulo = f2ord(Tf - DELTA);

    // ---- margin partition (ordered-uint compares) ----
    int nhi = 0, nbo = 0;
    #pragma unroll
    for (int s = 0; s < 16; s++) {
        nhi += (u[s] > Uhi) ? 1 : 0;
        nbo += (u[s] >= Ulo && u[s] <= Uhi) ? 1 : 0;
    }
    #pragma unroll
    for (int o = 16; o; o >>= 1) {
        nhi += __shfl_xor_sync(0xffffffffu, nhi, o);
        nbo += __shfl_xor_sync(0xffffffffu, nbo, o);
    }
    int r = k - nhi;

    bool win[16];
    if (nbo == r || nbo > 32) {
        unsigned Tcmp = (nbo > 32) ? T : Ulo;   // fallback to approx compare on overflow
        #pragma unroll
        for (int s = 0; s < 16; s++) win[s] = (u[s] >= Tcmp);
    } else {
        // ---- rare path: exact fp32 recompute of borderline elements ----
        if (lane < 16) s_bm[w][lane] = 0u;
        int base = 0;
        #pragma unroll
        for (int i = 0; i < 4; i++) {
            #pragma unroll
            for (int q = 0; q < 4; q++) {
                int s = i * 4 + q;
                bool isb = (u[s] >= Ulo && u[s] <= Uhi);
                unsigned m = __ballot_sync(0xffffffffu, isb);
                if (isb) {
                    int pos = base + __popc(m & ((1u << lane) - 1u));
                    s_bi[w][pos] = i * 128 + lane * 4 + q;
                }
                base += __popc(m);
            }
        }
        __syncwarp();
        int mcnt = base;
        const float* xi = x_in  + (size_t)b * DD;
        const float* xc = x_ctx + (size_t)b * DD;
        for (int e = 0; e < mcnt; e++) {
            int ncol = s_bi[w][e];
            const float* wf = Wff  + ((size_t)c * DD) * NN + ncol;
            const float* wc = Wctx + ((size_t)c * DD) * NN + ncol;
            float aff = 0.f, act2 = 0.f;
            #pragma unroll
            for (int t = 0; t < 8; t++) {
                int d = lane + t * 32;
                aff  = fmaf(xi[d], wf[(size_t)d * NN], aff);
                act2 = fmaf(xc[d], wc[(size_t)d * NN], act2);
            }
            #pragma unroll
            for (int o = 16; o; o >>= 1) {
                aff  += __shfl_xor_sync(0xffffffffu, aff,  o);
                act2 += __shfl_xor_sync(0xffffffffu, act2, o);
            }
            if (lane == 0)
                s_be[w][e] = aff + act2 * 0.3f + bias[(size_t)c * NN + ncol]
                           + g_boost[(size_t)c * NN + ncol];
            __syncwarp();
        }
        // exact rank among borderline; winners into bitmap
        if (lane < mcnt) {
            float v = s_be[w][lane];
            int g = 0;
            for (int j = 0; j < mcnt; j++) g += (s_be[w][j] > v) ? 1 : 0;
            if (g < r) {
                int col = s_bi[w][lane];
                atomicOr(&s_bm[w][col >> 5], 1u << (col & 31));
            }
        }
        __syncwarp();
        #pragma unroll
        for (int i = 0; i < 4; i++) {
            #pragma unroll
            for (int q = 0; q < 4; q++) {
                int s = i * 4 + q;
                int col = i * 128 + lane * 4 + q;
                bool inbm = (s_bm[w][col >> 5] >> (col & 31)) & 1u;
                win[s] = (u[s] > Uhi) || inbm;
            }
        }
    }

    // ---- normalization ----
    float lsum = 0.f;
    #pragma unroll
    for (int s = 0; s < 16; s++) {
        float rl = fmaxf(f[s], 0.f);
        lsum += win[s] ? rl : 0.f;
    }
    #pragma unroll
    for (int o = 16; o; o >>= 1) lsum += __shfl_xor_sync(0xffffffffu, lsum, o);
    float scale = (float)k / (lsum + 1e-8f);

    // ---- write act + compact nonzero winners ----
    float4* orow = reinterpret_cast<float4*>(act + (size_t)row * NN);
    int cnt_total = 0;
    #pragma unroll
    for (int i = 0; i < 4; i++) {
        float ov[4];
        #pragma unroll
        for (int q = 0; q < 4; q++) {
            int s = i * 4 + q;
            float rl  = fmaxf(f[s], 0.f);
            float val = win[s] ? rl * scale : 0.f;
            ov[q] = val;
            bool put = win[s] && (rl > 0.f);
            unsigned m = __ballot_sync(0xffffffffu, put);
            if (put) {
                int pos = cnt_total + __popc(m & ((1u << lane) - 1u));
                if (pos < 64) {
                    s_ii[w][pos] = i * 128 + lane * 4 + q;
                    s_vv[w][pos] = val;
                }
            }
            cnt_total += __popc(m);
        }
        orow[i * 32 + lane] = make_float4(ov[0], ov[1], ov[2], ov[3]);
    }
    if (cnt_total > 64) cnt_total = 64;
    __syncwarp();

    // ---- sparse prediction + error ----
    const float* WpC = Wp + (size_t)c * NN * DD;
    float4 acc0 = make_float4(0.f, 0.f, 0.f, 0.f);
    float4 acc1 = make_float4(0.f, 0.f, 0.f, 0.f);
    for (int j = 0; j < cnt_total; j++) {
        float vj = s_vv[w][j];
        const float4* wr = reinterpret_cast<const float4*>(WpC + (size_t)s_ii[w][j] * DD);
        float4 w0 = wr[lane];
        float4 w1 = wr[lane + 32];
        acc0.x = fmaf(vj, w0.x, acc0.x); acc0.y = fmaf(vj, w0.y, acc0.y);
        acc0.z = fmaf(vj, w0.z, acc0.z); acc0.w = fmaf(vj, w0.w, acc0.w);
        acc1.x = fmaf(vj, w1.x, acc1.x); acc1.y = fmaf(vj, w1.y, acc1.y);
        acc1.z = fmaf(vj, w1.z, acc1.z); acc1.w = fmaf(vj, w1.w, acc1.w);
    }

    const float4* xr = reinterpret_cast<const float4*>(x_in + (size_t)b * DD);
    float4 x0 = xr[lane], x1 = xr[lane + 32];
    float4* prow = reinterpret_cast<float4*>(pred + (size_t)row * DD);
    float4* erow = reinterpret_cast<float4*>(err  + (size_t)row * DD);
    prow[lane]      = acc0;
    prow[lane + 32] = acc1;
    erow[lane]      = make_float4(x0.x - acc0.x, x0.y - acc0.y, x0.z - acc0.z, x0.w - acc0.w);
    erow[lane + 32] = make_float4(x1.x - acc1.x, x1.y - acc1.y, x1.z - acc1.z, x1.w - acc1.w);
}

// ---------------------------------------------------------------------------
extern "C" void kernel_launch(void* const* d_in, const int* in_sizes, int n_in,
                              void* d_out, int out_size)
{
    const float* x_in  = (const float*)d_in[0];
    const float* x_ctx = (const float*)d_in[1];
    const float* Wff   = (const float*)d_in[2];
    const float* Wctx  = (const float*)d_in[3];
    const float* Wpred = (const float*)d_in[4];
    const float* bias  = (const float*)d_in[5];
    const float* avg   = (const float*)d_in[6];
    const int*   kptr  = (const int*)d_in[7];

    float* act  = (float*)d_out;                              // [B,C,N]
    float* pred = act  + (size_t)BB * CC * NN;                // [B,C,D]
    float* err  = pred + (size_t)BB * CC * DD;                // [B,C,D]

    boost_kernel<<<(CC * NN + 255) / 256, 256>>>(avg);

    dim3 g1(NN / 128, BB / 128, CC);
    drive_gemm<<<g1, 256>>>(x_in, x_ctx, Wff, Wctx, bias, act);

    topk_pred<<<BB * CC / 8, 256>>>(kptr, x_in, x_ctx, Wff, Wctx, bias,
                                    Wpred, act, pred, err);
}